// round 13
// baseline (speedup 1.0000x reference)
#include <cuda_runtime.h>
#include <math.h>
#include <stdint.h>

#define HEADS 8
#define AGENTS 49
#define WIN 32
#define BATCH 32
#define NTOK 1024
#define CH 256
#define HD 32
#define SCALE 0.17677669529663687f  // 32^-0.5

// ---------------- scratch (device globals; no runtime allocation) -----------
__device__ float g_q[BATCH*HEADS*NTOK*HD];    // (b,h,i,d)
__device__ float g_k[BATCH*HEADS*NTOK*HD];
__device__ float g_v[BATCH*HEADS*NTOK*HD];
__device__ float g_ah[BATCH*HEADS*AGENTS*HD]; // agent tokens, head layout
__device__ float g_pb[HEADS*AGENTS*NTOK];     // agent-attn position bias [h][a][i]
__device__ float g_ab[HEADS*AGENTS*NTOK];     // q-attn position bias, TRANSPOSED [h][a][i]
__device__ float g_av[BATCH*HEADS*AGENTS*HD]; // agent_v
__device__ float g_attn[BATCH*NTOK*CH];       // attention out + dwc (b,i,c)

__constant__ int c_starts[7] = {0,4,9,13,18,22,27};
__constant__ int c_ends[7]   = {5,10,14,19,23,28,32};

// ---------------- MUFU-free exp (FMA/ALU only); x <= 0, rel err ~3e-6 --------
__device__ __forceinline__ float exp_fast(float x) {
    x = fmaxf(x, -80.f);
    float y = x * 1.4426950408889634f;
    float r = y + 12582912.f;
    float t = r - 12582912.f;
    float f = y - t;
    int   n = __float_as_int(r);
    float p = 1.3333558146428443e-3f;
    p = fmaf(p, f, 9.6181291976746437e-3f);
    p = fmaf(p, f, 5.5504108664821580e-2f);
    p = fmaf(p, f, 2.4022650695910072e-1f);
    p = fmaf(p, f, 6.9314718055994531e-1f);
    p = fmaf(p, f, 1.0f);
    int e = (n - 1262485504 + 127) << 23;
    return p * __int_as_float(e);
}

// ---------------- tf32 helpers ----------------------------------------------
__device__ __forceinline__ uint32_t f2tf32(float f) {
    uint32_t r;
    asm("cvt.rna.tf32.f32 %0, %1;" : "=r"(r) : "f"(f));
    return r;
}

__device__ __forceinline__ void mma_tf32(float* c, const uint32_t* a, const uint32_t* b) {
    asm volatile(
        "mma.sync.aligned.m16n8k8.row.col.f32.tf32.tf32.f32 "
        "{%0,%1,%2,%3},{%4,%5,%6,%7},{%8,%9},{%0,%1,%2,%3};"
        : "+f"(c[0]), "+f"(c[1]), "+f"(c[2]), "+f"(c[3])
        : "r"(a[0]), "r"(a[1]), "r"(a[2]), "r"(a[3]), "r"(b[0]), "r"(b[1]));
}

// ---------------- tensor-core GEMM (tf32), BM=128 BN=128 BK=32, 256 thr ------
template<bool QKV>
__global__ __launch_bounds__(256) void gemm_tc(const float* __restrict__ x,
                                               const float* __restrict__ w,
                                               const float* __restrict__ bias,
                                               float* __restrict__ out) {
    __shared__ __align__(16) uint32_t As[128 * 36];
    __shared__ __align__(16) uint32_t Bs[128 * 36];
    const int tid = threadIdx.x;
    const int bm = blockIdx.y, bn = blockIdx.x;
    const int warp = tid >> 5, lane = tid & 31;
    const int g = lane >> 2, t = lane & 3;
    const int wm = warp >> 2, wn = warp & 3;
    const int M = QKV ? (BATCH * NTOK) : (BATCH * 1025);

    const float* aptr[4];
    const float* bptr[4];
    int soff[4];
    #pragma unroll
    for (int i = 0; i < 4; i++) {
        int j = tid + i * 256;
        int row = j >> 3;
        int col4 = (j & 7) << 2;
        soff[i] = row * 36 + col4;
        int gm = bm * 128 + row;
        if (QKV) {
            int b_ = gm >> 10, ii = gm & 1023;
            aptr[i] = x + (size_t)(b_ * 1025 + 1 + ii) * 256 + col4;
        } else {
            if (gm < M) {
                int b_ = gm / 1025, tt = gm % 1025;
                aptr[i] = (tt == 0) ? (x + (size_t)b_ * 1025 * 256 + col4)
                                    : (g_attn + (size_t)(b_ * 1024 + tt - 1) * 256 + col4);
            } else {
                aptr[i] = x + col4;
            }
        }
        bptr[i] = w + (size_t)(bn * 128 + row) * 256 + col4;
    }

    float acc[4][4][4] = {};

    for (int kc = 0; kc < 256; kc += 32) {
        #pragma unroll
        for (int i = 0; i < 4; i++) {
            float4 av = *(const float4*)(aptr[i] + kc);
            float4 bv = *(const float4*)(bptr[i] + kc);
            uint4 au = make_uint4(f2tf32(av.x), f2tf32(av.y), f2tf32(av.z), f2tf32(av.w));
            uint4 bu = make_uint4(f2tf32(bv.x), f2tf32(bv.y), f2tf32(bv.z), f2tf32(bv.w));
            *(uint4*)&As[soff[i]] = au;
            *(uint4*)&Bs[soff[i]] = bu;
        }
        __syncthreads();
        #pragma unroll
        for (int ks = 0; ks < 4; ks++) {
            const int kb = ks * 8;
            uint32_t af[4][4];
            #pragma unroll
            for (int mt = 0; mt < 4; mt++) {
                int mrow = wm * 64 + mt * 16 + g;
                af[mt][0] = As[mrow * 36 + kb + t];
                af[mt][1] = As[(mrow + 8) * 36 + kb + t];
                af[mt][2] = As[mrow * 36 + kb + t + 4];
                af[mt][3] = As[(mrow + 8) * 36 + kb + t + 4];
            }
            uint32_t bf[4][2];
            #pragma unroll
            for (int nt = 0; nt < 4; nt++) {
                int nrow = wn * 32 + nt * 8 + g;
                bf[nt][0] = Bs[nrow * 36 + kb + t];
                bf[nt][1] = Bs[nrow * 36 + kb + t + 4];
            }
            #pragma unroll
            for (int mt = 0; mt < 4; mt++)
                #pragma unroll
                for (int nt = 0; nt < 4; nt++)
                    mma_tf32(acc[mt][nt], af[mt], bf[nt]);
        }
        __syncthreads();
    }

    #pragma unroll
    for (int mt = 0; mt < 4; mt++) {
        #pragma unroll
        for (int nt = 0; nt < 4; nt++) {
            int coln = bn * 128 + wn * 32 + nt * 8 + 2 * t;
            #pragma unroll
            for (int half = 0; half < 2; half++) {
                int row = bm * 128 + wm * 64 + mt * 16 + g + half * 8;
                float v0 = acc[mt][nt][half * 2 + 0];
                float v1 = acc[mt][nt][half * 2 + 1];
                if (QKV) {
                    int b_ = row >> 10, i_ = row & 1023;
                    int tsel = coln >> 8, c_ = coln & 255;
                    int h = c_ >> 5, d = c_ & 31;
                    float* dst = (tsel == 0) ? g_q : (tsel == 1) ? g_k : g_v;
                    *(float2*)&dst[((size_t)(b_ * 8 + h) * 1024 + i_) * 32 + d] =
                        make_float2(v0, v1);
                } else {
                    if (row < M) {
                        *(float2*)&out[(size_t)row * 256 + coln] =
                            make_float2(v0 + bias[coln], v1 + bias[coln + 1]);
                    }
                }
            }
        }
    }
}

// ---------------- adaptive avg pool q -> agents ------------------------------
__global__ void pool_kernel() {
    int idx = blockIdx.x * 256 + threadIdx.x;
    if (idx >= BATCH * AGENTS * CH) return;
    int c = idx & 255;
    int a = (idx >> 8) % 49;
    int b = idx / (49 * 256);
    int ay = a / 7, ax = a % 7;
    int h = c >> 5, d = c & 31;
    const float* base = g_q + (size_t)(b * 8 + h) * 1024 * 32 + d;
    int ys = c_starts[ay], ye = c_ends[ay];
    int xs = c_starts[ax], xe = c_ends[ax];
    float s = 0.f;
    for (int y = ys; y < ye; y++)
        for (int xx = xs; xx < xe; xx++)
            s += base[(y * 32 + xx) * 32];
    s /= (float)((ye - ys) * (xe - xs));
    g_ah[((size_t)(b * 8 + h) * 49 + a) * 32 + d] = s;
}

// ---------------- bilinear 7x7 -> 32x32 (jax half-pixel == clamped bilerp) ---
__device__ __forceinline__ float bilerp7(const float* __restrict__ t, int y, int x) {
    float sy = (y + 0.5f) * 0.21875f - 0.5f;
    float sx = (x + 0.5f) * 0.21875f - 0.5f;
    sy = fminf(fmaxf(sy, 0.f), 6.f);
    sx = fminf(fmaxf(sx, 0.f), 6.f);
    int y0 = (int)sy, x0 = (int)sx;
    int y1 = min(y0 + 1, 6), x1 = min(x0 + 1, 6);
    float fy = sy - (float)y0, fx = sx - (float)x0;
    float v00 = t[y0 * 7 + x0], v01 = t[y0 * 7 + x1];
    float v10 = t[y1 * 7 + x0], v11 = t[y1 * 7 + x1];
    return (1.f - fy) * ((1.f - fx) * v00 + fx * v01)
         + fy * ((1.f - fx) * v10 + fx * v11);
}

__global__ void pb_kernel(const float* __restrict__ an,
                          const float* __restrict__ ahb,
                          const float* __restrict__ awb) {
    int idx = blockIdx.x * 256 + threadIdx.x;
    if (idx >= HEADS * AGENTS * NTOK) return;
    int x = idx & 31, y = (idx >> 5) & 31;
    int a = (idx >> 10) % 49, h = idx / (49 * 1024);
    float v = bilerp7(an + (h * 49 + a) * 49, y, x);
    v += ahb[(h * 49 + a) * 32 + y] + awb[(h * 49 + a) * 32 + x];
    g_pb[idx] = v;
}

// writes TRANSPOSED layout: g_ab[h][a][i]; h0 = head offset (split launches)
__global__ void ab_kernel(const float* __restrict__ na,
                          const float* __restrict__ hab,
                          const float* __restrict__ wab, int h0) {
    int idx = blockIdx.x * 256 + threadIdx.x;
    if (idx >= 4 * AGENTS * NTOK) return;
    int i = idx & 1023;
    int a = (idx >> 10) % 49;
    int h = h0 + idx / (49 * 1024);
    float v = bilerp7(na + (h * 49 + a) * 49, i >> 5, i & 31);
    v += hab[(h * 32 + (i >> 5)) * 49 + a] + wab[(h * 32 + (i & 31)) * 49 + a];
    g_ab[(size_t)h * 49 * 1024 + (size_t)a * 1024 + i] = v;
}

// ---------------- fused agent attention: softmax(ah@K^T*s + pb) @ V ----------
// grid (4, 256): x = agent quarter {13,12,12,12}, y = (b,h)
// P@V: warp owns 4 d-values, lane owns 4 toks; per-lane acc, butterfly at end
#define SS_PAD 132
__global__ __launch_bounds__(256) void agent_attn_fused() {
    __shared__ __align__(16) float Vt[32 * SS_PAD];   // [d][tok]
    __shared__ __align__(16) float ahs[13 * 32];
    __shared__ __align__(16) float Ss[13 * SS_PAD];   // [a][tok]
    __shared__ float m_s[13], l_s[13], scale_s[13];
    const int qx = blockIdx.x;
    const int A0 = (qx == 0) ? 0 : (13 + 12 * (qx - 1));
    const int NA = (qx == 0) ? 13 : 12;
    const int bh = blockIdx.y;
    const int tid = threadIdx.x;
    const int warp = tid >> 5, lane = tid & 31;
    const int h = bh & 7;
    const int d0 = warp * 4;
    for (int j = tid; j < NA * 32; j += 256) ahs[j] = g_ah[(size_t)bh * 1568 + A0 * 32 + j];
    if (tid < NA) { m_s[tid] = -1e30f; l_s[tid] = 0.f; }
    float acc[13][4] = {};
    const int half = tid >> 7;
    const int ii = tid & 127;
    const int nh0 = (NA + 1) >> 1;
    const int la0 = half ? nh0 : 0;
    const int lan = half ? (NA - nh0) : nh0;
    __syncthreads();

    for (int it = 0; it < 8; it++) {
        const int i0 = it * 128;
        // load V tile TRANSPOSED: Vt[d][tok]
        {
            const float4* src = (const float4*)(g_v + ((size_t)bh * 1024 + i0) * 32);
            for (int j = tid; j < 1024; j += 256) {
                int tok = j >> 3, d4 = (j & 7) << 2;
                float4 v = src[j];
                Vt[(d4 + 0) * SS_PAD + tok] = v.x;
                Vt[(d4 + 1) * SS_PAD + tok] = v.y;
                Vt[(d4 + 2) * SS_PAD + tok] = v.z;
                Vt[(d4 + 3) * SS_PAD + tok] = v.w;
            }
        }
        // scores
        {
            __align__(16) float kr[32];
            const float4* krow = (const float4*)(g_k + ((size_t)bh * 1024 + i0 + ii) * 32);
            #pragma unroll
            for (int j = 0; j < 8; j++) ((float4*)kr)[j] = krow[j];
            const float* pbb = g_pb + (size_t)h * 49 * 1024 + (size_t)A0 * 1024 + i0 + ii;
            for (int la = la0; la < la0 + lan; la++) {
                const float4* ar = (const float4*)&ahs[la * 32];
                float dot = 0.f;
                #pragma unroll
                for (int j = 0; j < 8; j++) {
                    float4 a4 = ar[j];
                    float4 k4 = ((const float4*)kr)[j];
                    dot += a4.x * k4.x + a4.y * k4.y + a4.z * k4.z + a4.w * k4.w;
                }
                Ss[la * SS_PAD + ii] = dot * SCALE + pbb[(size_t)la * 1024];
            }
        }
        __syncthreads();
        // per-agent tile max -> running max + rescale factor
        {
            int a = tid >> 2, q = tid & 3;
            float tm = -1e30f;
            if (a < NA) {
                const float4* row = (const float4*)&Ss[a * SS_PAD + q * 32];
                #pragma unroll
                for (int k2 = 0; k2 < 8; k2++) {
                    float4 v = row[k2];
                    tm = fmaxf(tm, fmaxf(fmaxf(v.x, v.y), fmaxf(v.z, v.w)));
                }
            }
            tm = fmaxf(tm, __shfl_xor_sync(0xffffffffu, tm, 1));
            tm = fmaxf(tm, __shfl_xor_sync(0xffffffffu, tm, 2));
            if (a < NA && q == 0) {
                float mo = m_s[a];
                float mn = fmaxf(mo, tm);
                scale_s[a] = exp_fast(mo - mn);
                m_s[a] = mn;
            }
        }
        __syncthreads();
        // exp in place + per-agent sum
        {
            int a = tid >> 2, q = tid & 3;
            float ts = 0.f;
            if (a < NA) {
                float mm = m_s[a];
                float4* row = (float4*)&Ss[a * SS_PAD + q * 32];
                #pragma unroll
                for (int k2 = 0; k2 < 8; k2++) {
                    float4 v = row[k2];
                    v.x = exp_fast(v.x - mm); v.y = exp_fast(v.y - mm);
                    v.z = exp_fast(v.z - mm); v.w = exp_fast(v.w - mm);
                    row[k2] = v;
                    ts += v.x + v.y + v.z + v.w;
                }
            }
            ts += __shfl_xor_sync(0xffffffffu, ts, 1);
            ts += __shfl_xor_sync(0xffffffffu, ts, 2);
            if (a < NA && q == 0) l_s[a] = l_s[a] * scale_s[a] + ts;
        }
        __syncthreads();
        // P @ V: warp owns d0..d0+3, lane owns toks {lane+32k}; conflict-free LDS.32
        {
            #pragma unroll
            for (int a = 0; a < 13; a++) {
                if (a < NA) {
                    float sc = scale_s[a];
                    acc[a][0] *= sc; acc[a][1] *= sc;
                    acc[a][2] *= sc; acc[a][3] *= sc;
                }
            }
            #pragma unroll
            for (int k = 0; k < 4; k++) {
                const int tok = k * 32 + lane;
                const float v0 = Vt[(d0 + 0) * SS_PAD + tok];
                const float v1 = Vt[(d0 + 1) * SS_PAD + tok];
                const float v2 = Vt[(d0 + 2) * SS_PAD + tok];
                const float v3 = Vt[(d0 + 3) * SS_PAD + tok];
                #pragma unroll
                for (int a = 0; a < 13; a++) {
                    if (a < NA) {
                        const float p = Ss[a * SS_PAD + tok];
                        acc[a][0] = fmaf(p, v0, acc[a][0]);
                        acc[a][1] = fmaf(p, v1, acc[a][1]);
                        acc[a][2] = fmaf(p, v2, acc[a][2]);
                        acc[a][3] = fmaf(p, v3, acc[a][3]);
                    }
                }
            }
        }
        __syncthreads();
    }

    // butterfly-reduce each (a, j) over lanes; lane a writes agent a's 4 d-values
    #pragma unroll
    for (int a = 0; a < 13; a++) {
        if (a < NA) {
            float4 o;
            float v;
            v = acc[a][0];
            v += __shfl_xor_sync(0xffffffffu, v, 16); v += __shfl_xor_sync(0xffffffffu, v, 8);
            v += __shfl_xor_sync(0xffffffffu, v, 4);  v += __shfl_xor_sync(0xffffffffu, v, 2);
            v += __shfl_xor_sync(0xffffffffu, v, 1);  o.x = v;
            v = acc[a][1];
            v += __shfl_xor_sync(0xffffffffu, v, 16); v += __shfl_xor_sync(0xffffffffu, v, 8);
            v += __shfl_xor_sync(0xffffffffu, v, 4);  v += __shfl_xor_sync(0xffffffffu, v, 2);
            v += __shfl_xor_sync(0xffffffffu, v, 1);  o.y = v;
            v = acc[a][2];
            v += __shfl_xor_sync(0xffffffffu, v, 16); v += __shfl_xor_sync(0xffffffffu, v, 8);
            v += __shfl_xor_sync(0xffffffffu, v, 4);  v += __shfl_xor_sync(0xffffffffu, v, 2);
            v += __shfl_xor_sync(0xffffffffu, v, 1);  o.z = v;
            v = acc[a][3];
            v += __shfl_xor_sync(0xffffffffu, v, 16); v += __shfl_xor_sync(0xffffffffu, v, 8);
            v += __shfl_xor_sync(0xffffffffu, v, 4);  v += __shfl_xor_sync(0xffffffffu, v, 2);
            v += __shfl_xor_sync(0xffffffffu, v, 1);  o.w = v;
            if (lane == a) {
                float inv = 1.f / l_s[a];
                o.x *= inv; o.y *= inv; o.z *= inv; o.w *= inv;
                *(float4*)&g_av[(size_t)bh * 1568 + (A0 + a) * 32 + d0] = o;
            }
        }
    }
}

// ---------------- fused q-attn + depthwise conv ------------------------------
#define VROW (34 * 33)
__global__ __launch_bounds__(128) void attn2_dwc_kernel(const float* __restrict__ dwc_w,
                                                        const float* __restrict__ dwc_b) {
    extern __shared__ __align__(16) float sm[];
    float* ahs = sm;
    float* avs = ahs + 1568;
    float* vsm = avs + 1568;
    float* wsm = vsm + 6 * VROW;
    float* bsm = wsm + 288;

    const int bh = blockIdx.y, itile = blockIdx.x, tid = threadIdx.x;
    const int h = bh & 7, b_ = bh >> 3;
    const int i0 = itile * 128;
    const int y0 = itile * 4;
    const int warp = tid >> 5, lane = tid & 31;

    for (int j = tid; j < 1568; j += 128) {
        ahs[j] = g_ah[(size_t)bh * 1568 + j];
        avs[j] = g_av[(size_t)bh * 1568 + j];
    }
    for (int j = tid; j < 288; j += 128) wsm[j] = dwc_w[(h * 32) * 9 + j];
    if (tid < 32) bsm[tid] = dwc_b[h * 32 + tid];
    for (int j = tid; j < 6 * VROW; j += 128) vsm[j] = 0.f;
    __syncthreads();

    for (int j = tid; j < 6 * 1024; j += 128) {
        int row = j >> 10;
        int rem = j & 1023;
        int x = rem >> 5, d = rem & 31;
        int gy = y0 - 1 + row;
        if (gy >= 0 && gy < 32)
            vsm[row * VROW + (x + 1) * 33 + d] =
                g_v[((size_t)bh * 1024 + gy * 32 + x) * 32 + d];
    }
    __syncthreads();

    const int i = i0 + tid;
    __align__(16) float q[32];
    const float4* qr = (const float4*)(g_q + ((size_t)bh * 1024 + i) * 32);
    #pragma unroll
    for (int j = 0; j < 8; j++) ((float4*)q)[j] = qr[j];
    const float* abg = g_ab + (size_t)h * 49 * 1024 + i;

    float s[49];
    float m = -1e30f;
    #pragma unroll
    for (int a = 0; a < 49; a++) {
        float dot = 0.f;
        #pragma unroll
        for (int d = 0; d < 32; d++) dot += q[d] * ahs[a * 32 + d];
        s[a] = dot * SCALE + abg[(size_t)a * 1024];
        m = fmaxf(m, s[a]);
    }
    float sum = 0.f;
    #pragma unroll
    for (int a = 0; a < 49; a++) {
        s[a] = exp_fast(s[a] - m);
        sum += s[a];
    }
    float inv = 1.f / sum;
    __align__(16) float out[32] = {};
    #pragma unroll
    for (int a = 0; a < 49; a++) {
        #pragma unroll
        for (int d = 0; d < 32; d++) out[d] += s[a] * avs[a * 32 + d];
    }

    const float* vrow0 = vsm + warp * VROW + lane * 33;
    #pragma unroll
    for (int d = 0; d < 32; d++) {
        float sdw = bsm[d];
        #pragma unroll
        for (int dy = 0; dy < 3; dy++) {
            const float* vr = vrow0 + dy * VROW + d;
            const float* wk = wsm + d * 9 + dy * 3;
            sdw += vr[0] * wk[0] + vr[33] * wk[1] + vr[66] * wk[2];
        }
        out[d] = out[d] * inv + sdw;
    }

    float* dst = g_attn + ((size_t)(b_ * 1024 + i) * 256) + h * 32;
    #pragma unroll
    for (int j = 0; j < 8; j++) ((float4*)dst)[j] = ((const float4*)out)[j];
}

// ---------------- launch ------------------------------------------------------
// ORDER NOTE: launch #4 = agent_attn_fused (verify the P@V restructure).
extern "C" void kernel_launch(void* const* d_in, const int* in_sizes, int n_in,
                              void* d_out, int out_size) {
    const float* x      = (const float*)d_in[0];
    const float* qkv_w  = (const float*)d_in[1];
    const float* proj_w = (const float*)d_in[2];
    const float* proj_b = (const float*)d_in[3];
    const float* dwc_w  = (const float*)d_in[4];
    const float* dwc_b  = (const float*)d_in[5];
    const float* an_b   = (const float*)d_in[6];
    const float* ah_b   = (const float*)d_in[7];
    const float* aw_b   = (const float*)d_in[8];
    const float* na_b   = (const float*)d_in[9];
    const float* ha_b   = (const float*)d_in[10];
    const float* wa_b   = (const float*)d_in[11];
    float* out = (float*)d_out;

    const int attn2_smem = (1568 + 1568 + 6 * VROW + 288 + 32) * 4;
    cudaFuncSetAttribute(attn2_dwc_kernel,
                         cudaFuncAttributeMaxDynamicSharedMemorySize, attn2_smem);

    const int abHalf = (4 * AGENTS * NTOK + 255) / 256;
    gemm_tc<true><<<dim3(6, 256), 256>>>(x, qkv_w, nullptr, nullptr);           // 1
    pool_kernel<<<(BATCH * AGENTS * CH + 255) / 256, 256>>>();                   // 2
    pb_kernel<<<(HEADS * AGENTS * NTOK + 255) / 256, 256>>>(an_b, ah_b, aw_b);   // 3
    agent_attn_fused<<<dim3(4, BATCH * HEADS), 256>>>();                         // 4 <- profiled
    ab_kernel<<<abHalf, 256>>>(na_b, ha_b, wa_b, 0);                             // 5
    ab_kernel<<<abHalf, 256>>>(na_b, ha_b, wa_b, 4);                             // 6
    attn2_dwc_kernel<<<dim3(8, 256), 128, attn2_smem>>>(dwc_w, dwc_b);           // 7
    gemm_tc<false><<<dim3(2, 257), 256>>>(x, proj_w, proj_b, out);               // 8
}

// round 14
// speedup vs baseline: 1.4057x; 1.4057x over previous
#include <cuda_runtime.h>
#include <math.h>
#include <stdint.h>

#define HEADS 8
#define AGENTS 49
#define WIN 32
#define BATCH 32
#define NTOK 1024
#define CH 256
#define HD 32
#define SCALE 0.17677669529663687f  // 32^-0.5

// ---------------- scratch (device globals; no runtime allocation) -----------
__device__ float g_q[BATCH*HEADS*NTOK*HD];    // (b,h,i,d)
__device__ float g_k[BATCH*HEADS*NTOK*HD];
__device__ float g_v[BATCH*HEADS*NTOK*HD];
__device__ float g_ah[BATCH*HEADS*AGENTS*HD]; // agent tokens, head layout
__device__ float g_pb[HEADS*AGENTS*NTOK];     // agent-attn position bias [h][a][i]
__device__ float g_ab[HEADS*AGENTS*NTOK];     // q-attn position bias, TRANSPOSED [h][a][i]
__device__ float g_av[BATCH*HEADS*AGENTS*HD]; // agent_v
__device__ float g_attn[BATCH*NTOK*CH];       // attention out + dwc (b,i,c)

__constant__ int c_starts[7] = {0,4,9,13,18,22,27};
__constant__ int c_ends[7]   = {5,10,14,19,23,28,32};

// ---------------- MUFU-free exp (FMA/ALU only); rel err ~3e-6 ----------------
__device__ __forceinline__ float exp_fast(float x) {
    x = fmaxf(x, -80.f);
    float y = x * 1.4426950408889634f;
    float r = y + 12582912.f;
    float t = r - 12582912.f;
    float f = y - t;
    int   n = __float_as_int(r);
    float p = 1.3333558146428443e-3f;
    p = fmaf(p, f, 9.6181291976746437e-3f);
    p = fmaf(p, f, 5.5504108664821580e-2f);
    p = fmaf(p, f, 2.4022650695910072e-1f);
    p = fmaf(p, f, 6.9314718055994531e-1f);
    p = fmaf(p, f, 1.0f);
    int e = (n - 1262485504 + 127) << 23;
    return p * __int_as_float(e);
}

// ---------------- tf32 helpers ----------------------------------------------
__device__ __forceinline__ uint32_t f2tf32(float f) {
    uint32_t r;
    asm("cvt.rna.tf32.f32 %0, %1;" : "=r"(r) : "f"(f));
    return r;
}
__device__ __forceinline__ float tf32r(float f) {   // rna-round to tf32, as float
    return __uint_as_float(f2tf32(f));
}

__device__ __forceinline__ void mma_tf32(float* c, const uint32_t* a, const uint32_t* b) {
    asm volatile(
        "mma.sync.aligned.m16n8k8.row.col.f32.tf32.tf32.f32 "
        "{%0,%1,%2,%3},{%4,%5,%6,%7},{%8,%9},{%0,%1,%2,%3};"
        : "+f"(c[0]), "+f"(c[1]), "+f"(c[2]), "+f"(c[3])
        : "r"(a[0]), "r"(a[1]), "r"(a[2]), "r"(a[3]), "r"(b[0]), "r"(b[1]));
}

// ---------------- tensor-core GEMM (tf32), BM=128 BN=128 BK=32, 256 thr ------
template<bool QKV>
__global__ __launch_bounds__(256) void gemm_tc(const float* __restrict__ x,
                                               const float* __restrict__ w,
                                               const float* __restrict__ bias,
                                               float* __restrict__ out) {
    __shared__ __align__(16) uint32_t As[128 * 36];
    __shared__ __align__(16) uint32_t Bs[128 * 36];
    const int tid = threadIdx.x;
    const int bm = blockIdx.y, bn = blockIdx.x;
    const int warp = tid >> 5, lane = tid & 31;
    const int g = lane >> 2, t = lane & 3;
    const int wm = warp >> 2, wn = warp & 3;
    const int M = QKV ? (BATCH * NTOK) : (BATCH * 1025);

    const float* aptr[4];
    const float* bptr[4];
    int soff[4];
    #pragma unroll
    for (int i = 0; i < 4; i++) {
        int j = tid + i * 256;
        int row = j >> 3;
        int col4 = (j & 7) << 2;
        soff[i] = row * 36 + col4;
        int gm = bm * 128 + row;
        if (QKV) {
            int b_ = gm >> 10, ii = gm & 1023;
            aptr[i] = x + (size_t)(b_ * 1025 + 1 + ii) * 256 + col4;
        } else {
            if (gm < M) {
                int b_ = gm / 1025, tt = gm % 1025;
                aptr[i] = (tt == 0) ? (x + (size_t)b_ * 1025 * 256 + col4)
                                    : (g_attn + (size_t)(b_ * 1024 + tt - 1) * 256 + col4);
            } else {
                aptr[i] = x + col4;
            }
        }
        bptr[i] = w + (size_t)(bn * 128 + row) * 256 + col4;
    }

    float acc[4][4][4] = {};

    for (int kc = 0; kc < 256; kc += 32) {
        #pragma unroll
        for (int i = 0; i < 4; i++) {
            float4 av = *(const float4*)(aptr[i] + kc);
            float4 bv = *(const float4*)(bptr[i] + kc);
            uint4 au = make_uint4(f2tf32(av.x), f2tf32(av.y), f2tf32(av.z), f2tf32(av.w));
            uint4 bu = make_uint4(f2tf32(bv.x), f2tf32(bv.y), f2tf32(bv.z), f2tf32(bv.w));
            *(uint4*)&As[soff[i]] = au;
            *(uint4*)&Bs[soff[i]] = bu;
        }
        __syncthreads();
        #pragma unroll
        for (int ks = 0; ks < 4; ks++) {
            const int kb = ks * 8;
            uint32_t af[4][4];
            #pragma unroll
            for (int mt = 0; mt < 4; mt++) {
                int mrow = wm * 64 + mt * 16 + g;
                af[mt][0] = As[mrow * 36 + kb + t];
                af[mt][1] = As[(mrow + 8) * 36 + kb + t];
                af[mt][2] = As[mrow * 36 + kb + t + 4];
                af[mt][3] = As[(mrow + 8) * 36 + kb + t + 4];
            }
            uint32_t bf[4][2];
            #pragma unroll
            for (int nt = 0; nt < 4; nt++) {
                int nrow = wn * 32 + nt * 8 + g;
                bf[nt][0] = Bs[nrow * 36 + kb + t];
                bf[nt][1] = Bs[nrow * 36 + kb + t + 4];
            }
            #pragma unroll
            for (int mt = 0; mt < 4; mt++)
                #pragma unroll
                for (int nt = 0; nt < 4; nt++)
                    mma_tf32(acc[mt][nt], af[mt], bf[nt]);
        }
        __syncthreads();
    }

    #pragma unroll
    for (int mt = 0; mt < 4; mt++) {
        #pragma unroll
        for (int nt = 0; nt < 4; nt++) {
            int coln = bn * 128 + wn * 32 + nt * 8 + 2 * t;
            #pragma unroll
            for (int half = 0; half < 2; half++) {
                int row = bm * 128 + wm * 64 + mt * 16 + g + half * 8;
                float v0 = acc[mt][nt][half * 2 + 0];
                float v1 = acc[mt][nt][half * 2 + 1];
                if (QKV) {
                    int b_ = row >> 10, i_ = row & 1023;
                    int tsel = coln >> 8, c_ = coln & 255;
                    int h = c_ >> 5, d = c_ & 31;
                    float* dst = (tsel == 0) ? g_q : (tsel == 1) ? g_k : g_v;
                    *(float2*)&dst[((size_t)(b_ * 8 + h) * 1024 + i_) * 32 + d] =
                        make_float2(v0, v1);
                } else {
                    if (row < M) {
                        *(float2*)&out[(size_t)row * 256 + coln] =
                            make_float2(v0 + bias[coln], v1 + bias[coln + 1]);
                    }
                }
            }
        }
    }
}

// ---------------- adaptive avg pool q -> agents ------------------------------
__global__ void pool_kernel() {
    int idx = blockIdx.x * 256 + threadIdx.x;
    if (idx >= BATCH * AGENTS * CH) return;
    int c = idx & 255;
    int a = (idx >> 8) % 49;
    int b = idx / (49 * 256);
    int ay = a / 7, ax = a % 7;
    int h = c >> 5, d = c & 31;
    const float* base = g_q + (size_t)(b * 8 + h) * 1024 * 32 + d;
    int ys = c_starts[ay], ye = c_ends[ay];
    int xs = c_starts[ax], xe = c_ends[ax];
    float s = 0.f;
    for (int y = ys; y < ye; y++)
        for (int xx = xs; xx < xe; xx++)
            s += base[(y * 32 + xx) * 32];
    s /= (float)((ye - ys) * (xe - xs));
    g_ah[((size_t)(b * 8 + h) * 49 + a) * 32 + d] = s;
}

// ---------------- bilinear 7x7 -> 32x32 (jax half-pixel == clamped bilerp) ---
__device__ __forceinline__ float bilerp7(const float* __restrict__ t, int y, int x) {
    float sy = (y + 0.5f) * 0.21875f - 0.5f;
    float sx = (x + 0.5f) * 0.21875f - 0.5f;
    sy = fminf(fmaxf(sy, 0.f), 6.f);
    sx = fminf(fmaxf(sx, 0.f), 6.f);
    int y0 = (int)sy, x0 = (int)sx;
    int y1 = min(y0 + 1, 6), x1 = min(x0 + 1, 6);
    float fy = sy - (float)y0, fx = sx - (float)x0;
    float v00 = t[y0 * 7 + x0], v01 = t[y0 * 7 + x1];
    float v10 = t[y1 * 7 + x0], v11 = t[y1 * 7 + x1];
    return (1.f - fy) * ((1.f - fx) * v00 + fx * v01)
         + fy * ((1.f - fx) * v10 + fx * v11);
}

__global__ void pb_kernel(const float* __restrict__ an,
                          const float* __restrict__ ahb,
                          const float* __restrict__ awb) {
    int idx = blockIdx.x * 256 + threadIdx.x;
    if (idx >= HEADS * AGENTS * NTOK) return;
    int x = idx & 31, y = (idx >> 5) & 31;
    int a = (idx >> 10) % 49, h = idx / (49 * 1024);
    float v = bilerp7(an + (h * 49 + a) * 49, y, x);
    v += ahb[(h * 49 + a) * 32 + y] + awb[(h * 49 + a) * 32 + x];
    g_pb[idx] = v;
}

// writes TRANSPOSED layout: g_ab[h][a][i]; h0 = head offset (split launches)
__global__ void ab_kernel(const float* __restrict__ na,
                          const float* __restrict__ hab,
                          const float* __restrict__ wab, int h0) {
    int idx = blockIdx.x * 256 + threadIdx.x;
    if (idx >= 4 * AGENTS * NTOK) return;
    int i = idx & 1023;
    int a = (idx >> 10) % 49;
    int h = h0 + idx / (49 * 1024);
    float v = bilerp7(na + (h * 49 + a) * 49, i >> 5, i & 31);
    v += hab[(h * 32 + (i >> 5)) * 49 + a] + wab[(h * 32 + (i & 31)) * 49 + a];
    g_ab[(size_t)h * 49 * 1024 + (size_t)a * 1024 + i] = v;
}

// ---------------- TENSOR-CORE fused agent attention ---------------------------
// block per (b,h), 256 thr / 8 warps, M padded 49->64.
// S = ah@K^T (mma tf32) +pb; exp (no max, |S|<~1); av += P@V (mma tf32).
// smem floats: ahs 64*36 | Kt 128*36 | Vt 32*132 | Ss 64*132 | l_s 64
#define AA_SMEM_FLOATS (64*36 + 128*36 + 32*132 + 64*132 + 64)
__global__ __launch_bounds__(256) void agent_attn_tc() {
    extern __shared__ __align__(16) float smp[];
    float* ahs = smp;                       // tf32 bits
    float* Kt  = ahs + 64 * 36;             // tf32 bits [tok][d]
    float* Vt  = Kt + 128 * 36;             // tf32 bits [d][tok]
    float* Ss  = Vt + 32 * 132;             // scores / probs [a][tok]
    float* l_s = Ss + 64 * 132;

    const int bh = blockIdx.x;
    const int tid = threadIdx.x;
    const int warp = tid >> 5, lane = tid & 31;
    const int g = lane >> 2, t = lane & 3;
    const int h = bh & 7;
    const int mt = warp >> 1;               // m-tile 0..3 (rows mt*16..+15)
    const int whalf = warp & 1;

    // load agents (tf32), zero-pad rows 49..63
    for (int j = tid; j < 64 * 32; j += 256) {
        int a = j >> 5, d = j & 31;
        float v = (a < 49) ? g_ah[(size_t)bh * 1568 + a * 32 + d] : 0.f;
        ahs[a * 36 + d] = tf32r(v);
    }
    if (tid < 64) l_s[tid] = 0.f;

    float pv[2][4] = {};                    // persistent P@V accumulators

    __syncthreads();

    for (int it = 0; it < 8; it++) {
        const int i0 = it * 128;
        // K tile -> Kt[tok][d] tf32
        {
            const float4* src = (const float4*)(g_k + ((size_t)bh * 1024 + i0) * 32);
            for (int j = tid; j < 1024; j += 256) {
                float4 v = src[j];
                float* dst = &Kt[(j >> 3) * 36 + ((j & 7) << 2)];
                dst[0] = tf32r(v.x); dst[1] = tf32r(v.y);
                dst[2] = tf32r(v.z); dst[3] = tf32r(v.w);
            }
        }
        // V tile -> Vt[d][tok] tf32
        {
            const float4* src = (const float4*)(g_v + ((size_t)bh * 1024 + i0) * 32);
            for (int j = tid; j < 1024; j += 256) {
                float4 v = src[j];
                int tok = j >> 3, d4 = (j & 7) << 2;
                Vt[(d4 + 0) * 132 + tok] = tf32r(v.x);
                Vt[(d4 + 1) * 132 + tok] = tf32r(v.y);
                Vt[(d4 + 2) * 132 + tok] = tf32r(v.z);
                Vt[(d4 + 3) * 132 + tok] = tf32r(v.w);
            }
        }
        __syncthreads();

        // scores mma: warp covers rows mt*16..+15, cols whalf*64..+63
        {
            float c[8][4] = {};
            const uint32_t* A = (const uint32_t*)ahs;
            const uint32_t* B = (const uint32_t*)Kt;
            #pragma unroll
            for (int ks = 0; ks < 4; ks++) {
                const int kb = ks * 8;
                uint32_t af[4];
                af[0] = A[(mt * 16 + g) * 36 + kb + t];
                af[1] = A[(mt * 16 + g + 8) * 36 + kb + t];
                af[2] = A[(mt * 16 + g) * 36 + kb + t + 4];
                af[3] = A[(mt * 16 + g + 8) * 36 + kb + t + 4];
                #pragma unroll
                for (int nt = 0; nt < 8; nt++) {
                    int nr = whalf * 64 + nt * 8 + g;
                    uint32_t bf[2] = { B[nr * 36 + kb + t], B[nr * 36 + kb + t + 4] };
                    mma_tf32(c[nt], af, bf);
                }
            }
            // writeback: *SCALE + pb (rows<49)
            const float* pbb = g_pb + (size_t)h * 49 * 1024 + i0;
            const int r0 = mt * 16 + g, r1 = r0 + 8;
            #pragma unroll
            for (int nt = 0; nt < 8; nt++) {
                int col = whalf * 64 + nt * 8 + 2 * t;
                float2 b0 = (r0 < 49) ? *(const float2*)&pbb[(size_t)r0 * 1024 + col]
                                      : make_float2(0.f, 0.f);
                float2 b1 = (r1 < 49) ? *(const float2*)&pbb[(size_t)r1 * 1024 + col]
                                      : make_float2(0.f, 0.f);
                *(float2*)&Ss[r0 * 132 + col] =
                    make_float2(fmaf(c[nt][0], SCALE, b0.x), fmaf(c[nt][1], SCALE, b0.y));
                *(float2*)&Ss[r1 * 132 + col] =
                    make_float2(fmaf(c[nt][2], SCALE, b1.x), fmaf(c[nt][3], SCALE, b1.y));
            }
        }
        __syncthreads();

        // exp (no max; |S| small) + l sum; values tf32-rounded for the PV mma
        {
            int a = tid >> 2, q = tid & 3;
            float ts = 0.f;
            float4* row = (float4*)&Ss[a * 132 + q * 32];
            #pragma unroll
            for (int k2 = 0; k2 < 8; k2++) {
                float4 v = row[k2];
                v.x = tf32r(exp_fast(v.x)); v.y = tf32r(exp_fast(v.y));
                v.z = tf32r(exp_fast(v.z)); v.w = tf32r(exp_fast(v.w));
                row[k2] = v;
                ts += v.x + v.y + v.z + v.w;
            }
            ts += __shfl_xor_sync(0xffffffffu, ts, 1);
            ts += __shfl_xor_sync(0xffffffffu, ts, 2);
            if (q == 0) l_s[a] += ts;
        }
        __syncthreads();

        // P@V mma: warp -> rows mt*16..+15, d-tiles {whalf*2, whalf*2+1}
        {
            const uint32_t* A = (const uint32_t*)Ss;
            const uint32_t* B = (const uint32_t*)Vt;
            #pragma unroll
            for (int ks = 0; ks < 16; ks++) {
                const int kb = ks * 8;
                uint32_t af[4];
                af[0] = A[(mt * 16 + g) * 132 + kb + t];
                af[1] = A[(mt * 16 + g + 8) * 132 + kb + t];
                af[2] = A[(mt * 16 + g) * 132 + kb + t + 4];
                af[3] = A[(mt * 16 + g + 8) * 132 + kb + t + 4];
                #pragma unroll
                for (int x = 0; x < 2; x++) {
                    int nr = (whalf * 2 + x) * 8 + g;
                    uint32_t bf[2] = { B[nr * 132 + kb + t], B[nr * 132 + kb + t + 4] };
                    mma_tf32(pv[x], af, bf);
                }
            }
        }
        __syncthreads();
    }

    // write av (rows < 49), normalized by l
    {
        const int r0 = mt * 16 + g, r1 = r0 + 8;
        #pragma unroll
        for (int x = 0; x < 2; x++) {
            int col = (whalf * 2 + x) * 8 + 2 * t;
            if (r0 < 49) {
                float inv = 1.f / l_s[r0];
                *(float2*)&g_av[(size_t)bh * 1568 + r0 * 32 + col] =
                    make_float2(pv[x][0] * inv, pv[x][1] * inv);
            }
            if (r1 < 49) {
                float inv = 1.f / l_s[r1];
                *(float2*)&g_av[(size_t)bh * 1568 + r1 * 32 + col] =
                    make_float2(pv[x][2] * inv, pv[x][3] * inv);
            }
        }
    }
}

// ---------------- fused q-attn + depthwise conv ------------------------------
#define VROW (34 * 33)
__global__ __launch_bounds__(128) void attn2_dwc_kernel(const float* __restrict__ dwc_w,
                                                        const float* __restrict__ dwc_b) {
    extern __shared__ __align__(16) float sm[];
    float* ahs = sm;
    float* avs = ahs + 1568;
    float* vsm = avs + 1568;
    float* wsm = vsm + 6 * VROW;
    float* bsm = wsm + 288;

    const int bh = blockIdx.y, itile = blockIdx.x, tid = threadIdx.x;
    const int h = bh & 7, b_ = bh >> 3;
    const int i0 = itile * 128;
    const int y0 = itile * 4;
    const int warp = tid >> 5, lane = tid & 31;

    for (int j = tid; j < 1568; j += 128) {
        ahs[j] = g_ah[(size_t)bh * 1568 + j];
        avs[j] = g_av[(size_t)bh * 1568 + j];
    }
    for (int j = tid; j < 288; j += 128) wsm[j] = dwc_w[(h * 32) * 9 + j];
    if (tid < 32) bsm[tid] = dwc_b[h * 32 + tid];
    for (int j = tid; j < 6 * VROW; j += 128) vsm[j] = 0.f;
    __syncthreads();

    for (int j = tid; j < 6 * 1024; j += 128) {
        int row = j >> 10;
        int rem = j & 1023;
        int x = rem >> 5, d = rem & 31;
        int gy = y0 - 1 + row;
        if (gy >= 0 && gy < 32)
            vsm[row * VROW + (x + 1) * 33 + d] =
                g_v[((size_t)bh * 1024 + gy * 32 + x) * 32 + d];
    }
    __syncthreads();

    const int i = i0 + tid;
    __align__(16) float q[32];
    const float4* qr = (const float4*)(g_q + ((size_t)bh * 1024 + i) * 32);
    #pragma unroll
    for (int j = 0; j < 8; j++) ((float4*)q)[j] = qr[j];
    const float* abg = g_ab + (size_t)h * 49 * 1024 + i;

    // no max-subtraction: scores are O(1), exp is safe and softmax shift-invariant
    float s[49];
    float sum = 0.f;
    #pragma unroll
    for (int a = 0; a < 49; a++) {
        float dot = 0.f;
        #pragma unroll
        for (int d = 0; d < 32; d++) dot += q[d] * ahs[a * 32 + d];
        s[a] = exp_fast(fmaf(dot, SCALE, abg[(size_t)a * 1024]));
        sum += s[a];
    }
    float inv = 1.f / sum;
    __align__(16) float out[32] = {};
    #pragma unroll
    for (int a = 0; a < 49; a++) {
        #pragma unroll
        for (int d = 0; d < 32; d++) out[d] += s[a] * avs[a * 32 + d];
    }

    const float* vrow0 = vsm + warp * VROW + lane * 33;
    #pragma unroll
    for (int d = 0; d < 32; d++) {
        float sdw = bsm[d];
        #pragma unroll
        for (int dy = 0; dy < 3; dy++) {
            const float* vr = vrow0 + dy * VROW + d;
            const float* wk = wsm + d * 9 + dy * 3;
            sdw += vr[0] * wk[0] + vr[33] * wk[1] + vr[66] * wk[2];
        }
        out[d] = out[d] * inv + sdw;
    }

    float* dst = g_attn + ((size_t)(b_ * 1024 + i) * 256) + h * 32;
    #pragma unroll
    for (int j = 0; j < 8; j++) ((float4*)dst)[j] = ((const float4*)out)[j];
}

// ---------------- launch ------------------------------------------------------
// ORDER NOTE: launch #4 = agent_attn_tc (verify the tensor-core rewrite).
extern "C" void kernel_launch(void* const* d_in, const int* in_sizes, int n_in,
                              void* d_out, int out_size) {
    const float* x      = (const float*)d_in[0];
    const float* qkv_w  = (const float*)d_in[1];
    const float* proj_w = (const float*)d_in[2];
    const float* proj_b = (const float*)d_in[3];
    const float* dwc_w  = (const float*)d_in[4];
    const float* dwc_b  = (const float*)d_in[5];
    const float* an_b   = (const float*)d_in[6];
    const float* ah_b   = (const float*)d_in[7];
    const float* aw_b   = (const float*)d_in[8];
    const float* na_b   = (const float*)d_in[9];
    const float* ha_b   = (const float*)d_in[10];
    const float* wa_b   = (const float*)d_in[11];
    float* out = (float*)d_out;

    const int attn2_smem = (1568 + 1568 + 6 * VROW + 288 + 32) * 4;
    cudaFuncSetAttribute(attn2_dwc_kernel,
                         cudaFuncAttributeMaxDynamicSharedMemorySize, attn2_smem);
    const int aa_smem = AA_SMEM_FLOATS * 4;   // ~78.6 KB
    cudaFuncSetAttribute(agent_attn_tc,
                         cudaFuncAttributeMaxDynamicSharedMemorySize, aa_smem);

    const int abHalf = (4 * AGENTS * NTOK + 255) / 256;
    gemm_tc<true><<<dim3(6, 256), 256>>>(x, qkv_w, nullptr, nullptr);           // 1
    pool_kernel<<<(BATCH * AGENTS * CH + 255) / 256, 256>>>();                   // 2
    pb_kernel<<<(HEADS * AGENTS * NTOK + 255) / 256, 256>>>(an_b, ah_b, aw_b);   // 3
    agent_attn_tc<<<BATCH * HEADS, 256, aa_smem>>>();                            // 4 <- profiled
    ab_kernel<<<abHalf, 256>>>(na_b, ha_b, wa_b, 0);                             // 5
    ab_kernel<<<abHalf, 256>>>(na_b, ha_b, wa_b, 4);                             // 6
    attn2_dwc_kernel<<<dim3(8, 256), 128, attn2_smem>>>(dwc_w, dwc_b);           // 7
    gemm_tc<false><<<dim3(2, 257), 256>>>(x, proj_w, proj_b, out);               // 8
}

// round 16
// speedup vs baseline: 1.4156x; 1.0070x over previous
#include <cuda_runtime.h>
#include <math.h>
#include <stdint.h>

#define HEADS 8
#define AGENTS 49
#define WIN 32
#define BATCH 32
#define NTOK 1024
#define CH 256
#define HD 32
#define SCALE 0.17677669529663687f  // 32^-0.5

// ---------------- scratch (device globals; no runtime allocation) -----------
__device__ float g_q[BATCH*HEADS*NTOK*HD];    // (b,h,i,d)
__device__ float g_k[BATCH*HEADS*NTOK*HD];
__device__ float g_v[BATCH*HEADS*NTOK*HD];
__device__ float g_ah[BATCH*HEADS*AGENTS*HD]; // agent tokens, head layout
__device__ float g_pb[HEADS*AGENTS*NTOK];     // agent-attn position bias [h][a][i]
__device__ float g_ab[HEADS*AGENTS*NTOK];     // q-attn position bias, TRANSPOSED [h][a][i]
__device__ float g_avp[2][BATCH*HEADS*AGENTS*HD]; // agent_v UNNORMALIZED partials
__device__ float g_lp[2][BATCH*HEADS*AGENTS];     // softmax-l partials
__device__ float g_attn[BATCH*NTOK*CH];       // attention out + dwc (b,i,c)

__constant__ int c_starts[7] = {0,4,9,13,18,22,27};
__constant__ int c_ends[7]   = {5,10,14,19,23,28,32};

// ---------------- MUFU-free exp (FMA/ALU only); rel err ~3e-6 ----------------
__device__ __forceinline__ float exp_fast(float x) {
    x = fmaxf(x, -80.f);
    float y = x * 1.4426950408889634f;
    float r = y + 12582912.f;
    float t = r - 12582912.f;
    float f = y - t;
    int   n = __float_as_int(r);
    float p = 1.3333558146428443e-3f;
    p = fmaf(p, f, 9.6181291976746437e-3f);
    p = fmaf(p, f, 5.5504108664821580e-2f);
    p = fmaf(p, f, 2.4022650695910072e-1f);
    p = fmaf(p, f, 6.9314718055994531e-1f);
    p = fmaf(p, f, 1.0f);
    int e = (n - 1262485504 + 127) << 23;
    return p * __int_as_float(e);
}

// ---------------- tf32 helpers ----------------------------------------------
__device__ __forceinline__ uint32_t f2tf32(float f) {
    uint32_t r;
    asm("cvt.rna.tf32.f32 %0, %1;" : "=r"(r) : "f"(f));
    return r;
}
__device__ __forceinline__ float tf32r(float f) {
    return __uint_as_float(f2tf32(f));
}

__device__ __forceinline__ void mma_tf32(float* c, const uint32_t* a, const uint32_t* b) {
    asm volatile(
        "mma.sync.aligned.m16n8k8.row.col.f32.tf32.tf32.f32 "
        "{%0,%1,%2,%3},{%4,%5,%6,%7},{%8,%9},{%0,%1,%2,%3};"
        : "+f"(c[0]), "+f"(c[1]), "+f"(c[2]), "+f"(c[3])
        : "r"(a[0]), "r"(a[1]), "r"(a[2]), "r"(a[3]), "r"(b[0]), "r"(b[1]));
}

// ---------------- tensor-core GEMM (tf32), BM=128 BN=128 BK=32, 256 thr ------
template<bool QKV>
__global__ __launch_bounds__(256) void gemm_tc(const float* __restrict__ x,
                                               const float* __restrict__ w,
                                               const float* __restrict__ bias,
                                               float* __restrict__ out) {
    __shared__ __align__(16) uint32_t As[128 * 36];
    __shared__ __align__(16) uint32_t Bs[128 * 36];
    const int tid = threadIdx.x;
    const int bm = blockIdx.y, bn = blockIdx.x;
    const int warp = tid >> 5, lane = tid & 31;
    const int g = lane >> 2, t = lane & 3;
    const int wm = warp >> 2, wn = warp & 3;
    const int M = QKV ? (BATCH * NTOK) : (BATCH * 1025);

    const float* aptr[4];
    const float* bptr[4];
    int soff[4];
    #pragma unroll
    for (int i = 0; i < 4; i++) {
        int j = tid + i * 256;
        int row = j >> 3;
        int col4 = (j & 7) << 2;
        soff[i] = row * 36 + col4;
        int gm = bm * 128 + row;
        if (QKV) {
            int b_ = gm >> 10, ii = gm & 1023;
            aptr[i] = x + (size_t)(b_ * 1025 + 1 + ii) * 256 + col4;
        } else {
            if (gm < M) {
                int b_ = gm / 1025, tt = gm % 1025;
                aptr[i] = (tt == 0) ? (x + (size_t)b_ * 1025 * 256 + col4)
                                    : (g_attn + (size_t)(b_ * 1024 + tt - 1) * 256 + col4);
            } else {
                aptr[i] = x + col4;
            }
        }
        bptr[i] = w + (size_t)(bn * 128 + row) * 256 + col4;
    }

    float acc[4][4][4] = {};

    for (int kc = 0; kc < 256; kc += 32) {
        #pragma unroll
        for (int i = 0; i < 4; i++) {
            float4 av = *(const float4*)(aptr[i] + kc);
            float4 bv = *(const float4*)(bptr[i] + kc);
            uint4 au = make_uint4(f2tf32(av.x), f2tf32(av.y), f2tf32(av.z), f2tf32(av.w));
            uint4 bu = make_uint4(f2tf32(bv.x), f2tf32(bv.y), f2tf32(bv.z), f2tf32(bv.w));
            *(uint4*)&As[soff[i]] = au;
            *(uint4*)&Bs[soff[i]] = bu;
        }
        __syncthreads();
        #pragma unroll
        for (int ks = 0; ks < 4; ks++) {
            const int kb = ks * 8;
            uint32_t af[4][4];
            #pragma unroll
            for (int mt = 0; mt < 4; mt++) {
                int mrow = wm * 64 + mt * 16 + g;
                af[mt][0] = As[mrow * 36 + kb + t];
                af[mt][1] = As[(mrow + 8) * 36 + kb + t];
                af[mt][2] = As[mrow * 36 + kb + t + 4];
                af[mt][3] = As[(mrow + 8) * 36 + kb + t + 4];
            }
            uint32_t bf[4][2];
            #pragma unroll
            for (int nt = 0; nt < 4; nt++) {
                int nrow = wn * 32 + nt * 8 + g;
                bf[nt][0] = Bs[nrow * 36 + kb + t];
                bf[nt][1] = Bs[nrow * 36 + kb + t + 4];
            }
            #pragma unroll
            for (int mt = 0; mt < 4; mt++)
                #pragma unroll
                for (int nt = 0; nt < 4; nt++)
                    mma_tf32(acc[mt][nt], af[mt], bf[nt]);
        }
        __syncthreads();
    }

    #pragma unroll
    for (int mt = 0; mt < 4; mt++) {
        #pragma unroll
        for (int nt = 0; nt < 4; nt++) {
            int coln = bn * 128 + wn * 32 + nt * 8 + 2 * t;
            #pragma unroll
            for (int half = 0; half < 2; half++) {
                int row = bm * 128 + wm * 64 + mt * 16 + g + half * 8;
                float v0 = acc[mt][nt][half * 2 + 0];
                float v1 = acc[mt][nt][half * 2 + 1];
                if (QKV) {
                    int b_ = row >> 10, i_ = row & 1023;
                    int tsel = coln >> 8, c_ = coln & 255;
                    int h = c_ >> 5, d = c_ & 31;
                    float* dst = (tsel == 0) ? g_q : (tsel == 1) ? g_k : g_v;
                    *(float2*)&dst[((size_t)(b_ * 8 + h) * 1024 + i_) * 32 + d] =
                        make_float2(v0, v1);
                } else {
                    if (row < M) {
                        *(float2*)&out[(size_t)row * 256 + coln] =
                            make_float2(v0 + bias[coln], v1 + bias[coln + 1]);
                    }
                }
            }
        }
    }
}

// ---------------- bilinear 7x7 -> 32x32 (jax half-pixel == clamped bilerp) ---
__device__ __forceinline__ float bilerp7(const float* __restrict__ t, int y, int x) {
    float sy = (y + 0.5f) * 0.21875f - 0.5f;
    float sx = (x + 0.5f) * 0.21875f - 0.5f;
    sy = fminf(fmaxf(sy, 0.f), 6.f);
    sx = fminf(fmaxf(sx, 0.f), 6.f);
    int y0 = (int)sy, x0 = (int)sx;
    int y1 = min(y0 + 1, 6), x1 = min(x0 + 1, 6);
    float fy = sy - (float)y0, fx = sx - (float)x0;
    float v00 = t[y0 * 7 + x0], v01 = t[y0 * 7 + x1];
    float v10 = t[y1 * 7 + x0], v11 = t[y1 * 7 + x1];
    return (1.f - fy) * ((1.f - fx) * v00 + fx * v01)
         + fy * ((1.f - fx) * v10 + fx * v11);
}

// ---------------- fused aux: pool | pb | ab in one launch ---------------------
// blocks [0,1568): pool; [1568,3136): pb; [3136,4704): ab
#define AUX_RANGE 1568
__global__ void aux_kernel(const float* __restrict__ an,
                           const float* __restrict__ ahb,
                           const float* __restrict__ awb,
                           const float* __restrict__ na,
                           const float* __restrict__ hab,
                           const float* __restrict__ wab) {
    int blk = blockIdx.x;
    if (blk < AUX_RANGE) {
        int idx = blk * 256 + threadIdx.x;          // pool
        int c = idx & 255;
        int a = (idx >> 8) % 49;
        int b = idx / (49 * 256);
        int ay = a / 7, ax = a % 7;
        int h = c >> 5, d = c & 31;
        const float* base = g_q + (size_t)(b * 8 + h) * 1024 * 32 + d;
        int ys = c_starts[ay], ye = c_ends[ay];
        int xs = c_starts[ax], xe = c_ends[ax];
        float s = 0.f;
        for (int y = ys; y < ye; y++)
            for (int xx = xs; xx < xe; xx++)
                s += base[(y * 32 + xx) * 32];
        s /= (float)((ye - ys) * (xe - xs));
        g_ah[((size_t)(b * 8 + h) * 49 + a) * 32 + d] = s;
    } else if (blk < 2 * AUX_RANGE) {
        int idx = (blk - AUX_RANGE) * 256 + threadIdx.x;  // pb
        int x = idx & 31, y = (idx >> 5) & 31;
        int a = (idx >> 10) % 49, h = idx / (49 * 1024);
        float v = bilerp7(an + (h * 49 + a) * 49, y, x);
        v += ahb[(h * 49 + a) * 32 + y] + awb[(h * 49 + a) * 32 + x];
        g_pb[idx] = v;
    } else {
        int idx = (blk - 2 * AUX_RANGE) * 256 + threadIdx.x;  // ab (transposed layout)
        int i = idx & 1023;
        int a = (idx >> 10) % 49;
        int h = idx / (49 * 1024);
        float v = bilerp7(na + (h * 49 + a) * 49, i >> 5, i & 31);
        v += hab[(h * 32 + (i >> 5)) * 49 + a] + wab[(h * 32 + (i & 31)) * 49 + a];
        g_ab[idx] = v;
    }
}

// ---------------- TENSOR-CORE agent attention, token-split partials ----------
// grid (2, 256): x = token half (4 tiles each), y = (b,h); 8 warps
// writes UNNORMALIZED pv + l partials; combine happens in attn2_dwc
#define AA_SMEM_FLOATS (64*36 + 128*36 + 32*132 + 64*132 + 64)
__global__ __launch_bounds__(256) void agent_attn_tc() {
    extern __shared__ __align__(16) float smp[];
    float* ahs = smp;
    float* Kt  = ahs + 64 * 36;
    float* Vt  = Kt + 128 * 36;
    float* Ss  = Vt + 32 * 132;
    float* l_s = Ss + 64 * 132;

    const int tk = blockIdx.x;
    const int bh = blockIdx.y;
    const int tid = threadIdx.x;
    const int warp = tid >> 5, lane = tid & 31;
    const int g = lane >> 2, t = lane & 3;
    const int h = bh & 7;
    const int mt = warp >> 1;
    const int whalf = warp & 1;

    for (int j = tid; j < 64 * 32; j += 256) {
        int a = j >> 5, d = j & 31;
        float v = (a < 49) ? g_ah[(size_t)bh * 1568 + a * 32 + d] : 0.f;
        ahs[a * 36 + d] = tf32r(v);
    }
    if (tid < 64) l_s[tid] = 0.f;

    float pv[2][4] = {};
    __syncthreads();

    for (int it = tk * 4; it < tk * 4 + 4; it++) {
        const int i0 = it * 128;
        {
            const float4* src = (const float4*)(g_k + ((size_t)bh * 1024 + i0) * 32);
            for (int j = tid; j < 1024; j += 256) {
                float4 v = src[j];
                float* dst = &Kt[(j >> 3) * 36 + ((j & 7) << 2)];
                dst[0] = tf32r(v.x); dst[1] = tf32r(v.y);
                dst[2] = tf32r(v.z); dst[3] = tf32r(v.w);
            }
        }
        {
            const float4* src = (const float4*)(g_v + ((size_t)bh * 1024 + i0) * 32);
            for (int j = tid; j < 1024; j += 256) {
                float4 v = src[j];
                int tok = j >> 3, d4 = (j & 7) << 2;
                Vt[(d4 + 0) * 132 + tok] = tf32r(v.x);
                Vt[(d4 + 1) * 132 + tok] = tf32r(v.y);
                Vt[(d4 + 2) * 132 + tok] = tf32r(v.z);
                Vt[(d4 + 3) * 132 + tok] = tf32r(v.w);
            }
        }
        __syncthreads();

        // scores mma
        {
            float c[8][4] = {};
            const uint32_t* A = (const uint32_t*)ahs;
            const uint32_t* B = (const uint32_t*)Kt;
            #pragma unroll
            for (int ks = 0; ks < 4; ks++) {
                const int kb = ks * 8;
                uint32_t af[4];
                af[0] = A[(mt * 16 + g) * 36 + kb + t];
                af[1] = A[(mt * 16 + g + 8) * 36 + kb + t];
                af[2] = A[(mt * 16 + g) * 36 + kb + t + 4];
                af[3] = A[(mt * 16 + g + 8) * 36 + kb + t + 4];
                #pragma unroll
                for (int nt = 0; nt < 8; nt++) {
                    int nr = whalf * 64 + nt * 8 + g;
                    uint32_t bf[2] = { B[nr * 36 + kb + t], B[nr * 36 + kb + t + 4] };
                    mma_tf32(c[nt], af, bf);
                }
            }
            const float* pbb = g_pb + (size_t)h * 49 * 1024 + i0;
            const int r0 = mt * 16 + g, r1 = r0 + 8;
            #pragma unroll
            for (int nt = 0; nt < 8; nt++) {
                int col = whalf * 64 + nt * 8 + 2 * t;
                float2 b0 = (r0 < 49) ? *(const float2*)&pbb[(size_t)r0 * 1024 + col]
                                      : make_float2(0.f, 0.f);
                float2 b1 = (r1 < 49) ? *(const float2*)&pbb[(size_t)r1 * 1024 + col]
                                      : make_float2(0.f, 0.f);
                *(float2*)&Ss[r0 * 132 + col] =
                    make_float2(fmaf(c[nt][0], SCALE, b0.x), fmaf(c[nt][1], SCALE, b0.y));
                *(float2*)&Ss[r1 * 132 + col] =
                    make_float2(fmaf(c[nt][2], SCALE, b1.x), fmaf(c[nt][3], SCALE, b1.y));
            }
        }
        __syncthreads();

        // exp (no max) + l partial sum
        {
            int a = tid >> 2, q = tid & 3;
            float ts = 0.f;
            float4* row = (float4*)&Ss[a * 132 + q * 32];
            #pragma unroll
            for (int k2 = 0; k2 < 8; k2++) {
                float4 v = row[k2];
                v.x = tf32r(exp_fast(v.x)); v.y = tf32r(exp_fast(v.y));
                v.z = tf32r(exp_fast(v.z)); v.w = tf32r(exp_fast(v.w));
                row[k2] = v;
                ts += v.x + v.y + v.z + v.w;
            }
            ts += __shfl_xor_sync(0xffffffffu, ts, 1);
            ts += __shfl_xor_sync(0xffffffffu, ts, 2);
            if (q == 0) l_s[a] += ts;
        }
        __syncthreads();

        // P@V mma
        {
            const uint32_t* A = (const uint32_t*)Ss;
            const uint32_t* B = (const uint32_t*)Vt;
            #pragma unroll
            for (int ks = 0; ks < 16; ks++) {
                const int kb = ks * 8;
                uint32_t af[4];
                af[0] = A[(mt * 16 + g) * 132 + kb + t];
                af[1] = A[(mt * 16 + g + 8) * 132 + kb + t];
                af[2] = A[(mt * 16 + g) * 132 + kb + t + 4];
                af[3] = A[(mt * 16 + g + 8) * 132 + kb + t + 4];
                #pragma unroll
                for (int x = 0; x < 2; x++) {
                    int nr = (whalf * 2 + x) * 8 + g;
                    uint32_t bf[2] = { B[nr * 132 + kb + t], B[nr * 132 + kb + t + 4] };
                    mma_tf32(pv[x], af, bf);
                }
            }
        }
        __syncthreads();
    }

    // write UNNORMALIZED pv + l partials
    {
        float* avp = g_avp[tk];
        const int r0 = mt * 16 + g, r1 = r0 + 8;
        #pragma unroll
        for (int x = 0; x < 2; x++) {
            int col = (whalf * 2 + x) * 8 + 2 * t;
            if (r0 < 49)
                *(float2*)&avp[(size_t)bh * 1568 + r0 * 32 + col] =
                    make_float2(pv[x][0], pv[x][1]);
            if (r1 < 49)
                *(float2*)&avp[(size_t)bh * 1568 + r1 * 32 + col] =
                    make_float2(pv[x][2], pv[x][3]);
        }
        if (tid < 49) g_lp[tk][(size_t)bh * 49 + tid] = l_s[tid];
    }
}

// ---------------- fused q-attn + depthwise conv (+ partial combine) ----------
#define VROW (34 * 33)
__global__ __launch_bounds__(128) void attn2_dwc_kernel(const float* __restrict__ dwc_w,
                                                        const float* __restrict__ dwc_b) {
    extern __shared__ __align__(16) float sm[];
    float* ahs  = sm;
    float* avs  = ahs + 1568;
    float* vsm  = avs + 1568;
    float* wsm  = vsm + 6 * VROW;
    float* bsm  = wsm + 288;
    float* lrec = bsm + 32;     // [52]

    const int bh = blockIdx.y, itile = blockIdx.x, tid = threadIdx.x;
    const int h = bh & 7, b_ = bh >> 3;
    const int i0 = itile * 128;
    const int y0 = itile * 4;
    const int warp = tid >> 5, lane = tid & 31;

    const float* avp0 = g_avp[0] + (size_t)bh * 1568;
    const float* avp1 = g_avp[1] + (size_t)bh * 1568;
    for (int j = tid; j < 1568; j += 128) {
        ahs[j] = g_ah[(size_t)bh * 1568 + j];
        avs[j] = avp0[j] + avp1[j];
    }
    if (tid < 49)
        lrec[tid] = 1.f / (g_lp[0][(size_t)bh * 49 + tid] + g_lp[1][(size_t)bh * 49 + tid]);
    for (int j = tid; j < 288; j += 128) wsm[j] = dwc_w[(h * 32) * 9 + j];
    if (tid >= 64 && tid < 96) bsm[tid - 64] = dwc_b[h * 32 + tid - 64];
    for (int j = tid; j < 6 * VROW; j += 128) vsm[j] = 0.f;
    __syncthreads();

    for (int j = tid; j < 6 * 1024; j += 128) {
        int row = j >> 10;
        int rem = j & 1023;
        int x = rem >> 5, d = rem & 31;
        int gy = y0 - 1 + row;
        if (gy >= 0 && gy < 32)
            vsm[row * VROW + (x + 1) * 33 + d] =
                g_v[((size_t)bh * 1024 + gy * 32 + x) * 32 + d];
    }
    __syncthreads();

    const int i = i0 + tid;
    __align__(16) float q[32];
    const float4* qr = (const float4*)(g_q + ((size_t)bh * 1024 + i) * 32);
    #pragma unroll
    for (int j = 0; j < 8; j++) ((float4*)q)[j] = qr[j];
    const float* abg = g_ab + (size_t)h * 49 * 1024 + i;

    // no max-subtraction (scores O(1), softmax shift-invariant)
    float s[49];
    float sum = 0.f;
    #pragma unroll
    for (int a = 0; a < 49; a++) {
        float dot = 0.f;
        #pragma unroll
        for (int d = 0; d < 32; d++) dot += q[d] * ahs[a * 32 + d];
        s[a] = exp_fast(fmaf(dot, SCALE, abg[(size_t)a * 1024]));
        sum += s[a];
    }
    float inv = 1.f / sum;
    __align__(16) float out[32] = {};
    #pragma unroll
    for (int a = 0; a < 49; a++) {
        float w = s[a] * lrec[a];   // fold agent_v normalization into weight
        #pragma unroll
        for (int d = 0; d < 32; d++) out[d] += w * avs[a * 32 + d];
    }

    const float* vrow0 = vsm + warp * VROW + lane * 33;
    #pragma unroll
    for (int d = 0; d < 32; d++) {
        float sdw = bsm[d];
        #pragma unroll
        for (int dy = 0; dy < 3; dy++) {
            const float* vr = vrow0 + dy * VROW + d;
            const float* wk = wsm + d * 9 + dy * 3;
            sdw += vr[0] * wk[0] + vr[33] * wk[1] + vr[66] * wk[2];
        }
        out[d] = out[d] * inv + sdw;
    }

    float* dst = g_attn + ((size_t)(b_ * 1024 + i) * 256) + h * 32;
    #pragma unroll
    for (int j = 0; j < 8; j++) ((float4*)dst)[j] = ((const float4*)out)[j];
}

// ---------------- launch ------------------------------------------------------
// ORDER NOTE: launch #4 = attn2_dwc_kernel (first measurement of it).
extern "C" void kernel_launch(void* const* d_in, const int* in_sizes, int n_in,
                              void* d_out, int out_size) {
    const float* x      = (const float*)d_in[0];
    const float* qkv_w  = (const float*)d_in[1];
    const float* proj_w = (const float*)d_in[2];
    const float* proj_b = (const float*)d_in[3];
    const float* dwc_w  = (const float*)d_in[4];
    const float* dwc_b  = (const float*)d_in[5];
    const float* an_b   = (const float*)d_in[6];
    const float* ah_b   = (const float*)d_in[7];
    const float* aw_b   = (const float*)d_in[8];
    const float* na_b   = (const float*)d_in[9];
    const float* ha_b   = (const float*)d_in[10];
    const float* wa_b   = (const float*)d_in[11];
    float* out = (float*)d_out;

    const int attn2_smem = (1568 + 1568 + 6 * VROW + 288 + 32 + 52) * 4;
    cudaFuncSetAttribute(attn2_dwc_kernel,
                         cudaFuncAttributeMaxDynamicSharedMemorySize, attn2_smem);
    const int aa_smem = AA_SMEM_FLOATS * 4;
    cudaFuncSetAttribute(agent_attn_tc,
                         cudaFuncAttributeMaxDynamicSharedMemorySize, aa_smem);

    gemm_tc<true><<<dim3(6, 256), 256>>>(x, qkv_w, nullptr, nullptr);            // 1
    aux_kernel<<<3 * AUX_RANGE, 256>>>(an_b, ah_b, aw_b, na_b, ha_b, wa_b);      // 2
    agent_attn_tc<<<dim3(2, BATCH * HEADS), 256, aa_smem>>>();                   // 3
    attn2_dwc_kernel<<<dim3(8, 256), 128, attn2_smem>>>(dwc_w, dwc_b);           // 4 <- profiled
    gemm_tc<false><<<dim3(2, 257), 256>>>(x, proj_w, proj_b, out);               // 5
}